// round 16
// baseline (speedup 1.0000x reference)
#include <cuda_runtime.h>
#include <cuda_bf16.h>
#include <cuda_fp16.h>
#include <cstdint>

#define NTX_MAX 100000
#define NM_MAX  20000
#define E_MAX   500000

typedef __nv_bfloat16 bf16;

// ---------------- scratch (static device globals; no runtime allocation) ----------------
__device__ float  g_q_tx [(size_t)NTX_MAX * 64];   // fp32 Q
__device__ float  g_q_m  [(size_t)NM_MAX  * 64];
__device__ __half g_kv_tx[(size_t)NTX_MAX * 128];  // fp16 [Khat | Vhat]
__device__ __half g_kv_m [(size_t)NM_MAX  * 128];
__device__ float  g_agg_tx[(size_t)NTX_MAX * 64];
__device__ float  g_agg_m [(size_t)NM_MAX  * 64];
__device__ float  g_h_tx  [(size_t)NTX_MAX * 64];  // fp32 (skip input for L2 epilogue)
__device__ float  g_WA1[128 * 192];  __device__ float g_bA1[192];
__device__ float  g_WB1[128 * 192];  __device__ float g_bB1[192];
__device__ float  g_WA2[128 * 192];  __device__ float g_bA2[192];
__device__ float  g_WB2[128 * 192];  __device__ float g_bB2[192];
// CSR
__device__ int g_rowptr0[NM_MAX + 1];   // dst = m   (tx->m edges)
__device__ int g_rowptr1[NTX_MAX + 1];  // dst = tx  (m->tx edges)
__device__ int g_cursor0[NM_MAX];
__device__ int g_cursor1[NTX_MAX];
__device__ int g_srcs0[E_MAX];
__device__ int g_srcs1[E_MAX];

// ---------------- CSR build ----------------
__global__ void hist_both_kernel(const int* __restrict__ d0, int E0, int* __restrict__ c0,
                                 const int* __restrict__ d1, int E1, int* __restrict__ c1) {
    int e = blockIdx.x * blockDim.x + threadIdx.x;
    if (e < E0) atomicAdd(&c0[d0[e]], 1);
    else if (e < E0 + E1) atomicAdd(&c1[d1[e - E0]], 1);
}

__global__ void scan_both_kernel(int* __restrict__ cnt0, int* __restrict__ rp0, int n0,
                                 int* __restrict__ cnt1, int* __restrict__ rp1, int n1) {
    __shared__ int ssum[1024];
    int* cnt = blockIdx.x ? cnt1 : cnt0;
    int* rowptr = blockIdx.x ? rp1 : rp0;
    int n = blockIdx.x ? n1 : n0;
    int tid = threadIdx.x;
    int chunk = (n + 1023) / 1024;
    int start = tid * chunk;
    int end = start + chunk; if (end > n) end = n; if (start > n) start = n;
    int s = 0;
    for (int i = start; i < end; i++) s += cnt[i];
    ssum[tid] = s;
    __syncthreads();
    for (int off = 1; off < 1024; off <<= 1) {
        int v = (tid >= off) ? ssum[tid - off] : 0;
        __syncthreads();
        ssum[tid] += v;
        __syncthreads();
    }
    int run = (tid == 0) ? 0 : ssum[tid - 1];
    for (int i = start; i < end; i++) {
        int c = cnt[i];
        rowptr[i] = run;
        cnt[i] = run;       // cursor = rowptr (cnt doubles as cursor)
        run += c;
    }
    if (tid == 1023) rowptr[n] = run;
}

// ---------------- effective fused weights + CSR zeroing, one launch ----------------
__global__ void eff_all_kernel(
    const float* c1_Wq, const float* c1_bq, const float* c1_Wk, const float* c1_bk,
    const float* c1_Wv, const float* c1_bv, const float* c1_a, const float* c1_m,
    const float* c2_Wq, const float* c2_bq, const float* c2_Wk, const float* c2_bk,
    const float* c2_Wv, const float* c2_bv, const float* c2_a, const float* c2_m,
    float* WA1, float* bA1, float* WB1, float* bB1,
    float* WA2, float* bA2, float* WB2, float* bB2,
    int* cur0, int n0, int* cur1, int n1) {
    int y = blockIdx.y;
    int idx = blockIdx.x * blockDim.x + threadIdx.x;
    if (y == 4) {
        if (idx < n0) cur0[idx] = 0;
        else if (idx < n0 + n1) cur1[idx - n0] = 0;
        return;
    }
    int layer = y >> 1, typ = y & 1;
    int din = layer ? 64 : 128;
    int total = (din + 1) * 192;
    if (idx >= total) return;
    const float* Wq = layer ? c2_Wq : c1_Wq;  const float* bq = layer ? c2_bq : c1_bq;
    const float* Wk = layer ? c2_Wk : c1_Wk;  const float* bk = layer ? c2_bk : c1_bk;
    const float* Wv = layer ? c2_Wv : c1_Wv;  const float* bv = layer ? c2_bv : c1_bv;
    const float* ar = layer ? c2_a : c1_a;    const float* mr = layer ? c2_m : c1_m;
    Wq += (size_t)typ * din * 64; bq += typ * 64;
    Wk += (size_t)typ * din * 64; bk += typ * 64;
    Wv += (size_t)typ * din * 64; bv += typ * 64;
    ar += typ * 1024; mr += typ * 1024;
    float* Wout = layer ? (typ ? WB2 : WA2) : (typ ? WB1 : WA1);
    float* bout = layer ? (typ ? bB2 : bA2) : (typ ? bB1 : bA1);

    int i = idx / 192, c = idx % 192;
    bool isBias = (i == din);
    float val;
    if (c < 64) {
        val = isBias ? bq[c] : Wq[i * 64 + c];
    } else {
        int cc = c - 64;
        bool isV = (cc >= 64);
        if (isV) cc -= 64;
        int h = cc >> 4, e = cc & 15;
        const float* rel  = isV ? mr : ar;
        const float* Wsrc = isV ? Wv : Wk;
        const float* bsrc = isV ? bv : bk;
        float s = 0.f;
        #pragma unroll
        for (int d = 0; d < 16; d++) {
            float w = isBias ? bsrc[h * 16 + d] : Wsrc[i * 64 + h * 16 + d];
            s += w * rel[h * 256 + d * 16 + e];
        }
        val = s;
    }
    if (isBias) bout[c] = val;
    else        Wout[i * 192 + c] = val;
}

// ---------------- common GEMM device helpers ----------------
__device__ __forceinline__ void ldsm_x4(uint32_t* r, uint32_t addr) {
    asm volatile("ldmatrix.sync.aligned.m8n8.x4.shared.b16 {%0,%1,%2,%3}, [%4];"
        : "=r"(r[0]), "=r"(r[1]), "=r"(r[2]), "=r"(r[3]) : "r"(addr));
}
__device__ __forceinline__ void ldsm_x4_t(uint32_t* r, uint32_t addr) {
    asm volatile("ldmatrix.sync.aligned.m8n8.x4.trans.shared.b16 {%0,%1,%2,%3}, [%4];"
        : "=r"(r[0]), "=r"(r[1]), "=r"(r[2]), "=r"(r[3]) : "r"(addr));
}
__device__ __forceinline__ void mma_bf16(float* c, const uint32_t* a, uint32_t b0, uint32_t b1) {
    asm volatile("mma.sync.aligned.m16n8k16.row.col.f32.bf16.bf16.f32 "
        "{%0,%1,%2,%3}, {%4,%5,%6,%7}, {%8,%9}, {%0,%1,%2,%3};"
        : "+f"(c[0]), "+f"(c[1]), "+f"(c[2]), "+f"(c[3])
        : "r"(a[0]), "r"(a[1]), "r"(a[2]), "r"(a[3]), "r"(b0), "r"(b1));
}

__device__ __forceinline__ void split2(float x, float y, uint32_t& hi, uint32_t& lo) {
    bf16 hx = __float2bfloat16_rn(x), hy = __float2bfloat16_rn(y);
    bf16 lx = __float2bfloat16_rn(x - __bfloat162float(hx));
    bf16 ly = __float2bfloat16_rn(y - __bfloat162float(hy));
    __nv_bfloat162 h2 = __halves2bfloat162(hx, hy);
    __nv_bfloat162 l2 = __halves2bfloat162(lx, ly);
    hi = *(uint32_t*)&h2;
    lo = *(uint32_t*)&l2;
}

__device__ __forceinline__ float gelu_exact(float v) {
    return 0.5f * v * (1.f + erff(v * 0.70710678118654752f));
}

#define AS_STRIDE 40   // 32 + 8 pad (bf16 elems): conflict-free ldmatrix

struct GemmJob {
    const float* A; const float* B; const float* bias; const float* x_in;
    float* outF; __half* outH;
    int N, ldb, col0, ldo, colBlocks;
};

struct ScatJob {
    const int* s0; const int* d0; int E0; int* cur0; int* out0;
    const int* s1; const int* d1; int E1; int* cur1; int* out1;
    int nblocks;
};

// ---------------- generic 128-row GEMM (R10) ----------------
template <int POST, int AGELU, int NCOLS, int SCAT, int FINAL>
__global__ __launch_bounds__(256) void mma_gemm_kernel(
    GemmJob j0, GemmJob j1, int nb0, int DIN, const float* __restrict__ skipv,
    ScatJob sj, const float* __restrict__ Wc, const float* __restrict__ bc) {
    constexpr int NH = NCOLS / 2;
    constexpr int J2N = NH / 16;
    constexpr int JN = NH / 8;
    constexpr int BSTR = NCOLS + 8;
    constexpr int BQ = NCOLS / 4;
    constexpr int NB = NCOLS / 32;
    __shared__ bf16 As[2][128 * AS_STRIDE];
    __shared__ bf16 Bs[2][32 * BSTR];
    __shared__ float sred[FINAL ? 128 : 1];

    int t = threadIdx.x;
    if (SCAT) {
        if (blockIdx.x < (unsigned)sj.nblocks) {
            int e = blockIdx.x * 256 + t;
            if (e < sj.E0) {
                int p = atomicAdd(&sj.cur0[sj.d0[e]], 1);
                sj.out0[p] = sj.s0[e];
            } else if (e < sj.E0 + sj.E1) {
                int ee = e - sj.E0;
                int p = atomicAdd(&sj.cur1[sj.d1[ee]], 1);
                sj.out1[p] = sj.s1[ee];
            }
            return;
        }
    }
    int bx = blockIdx.x - (SCAT ? sj.nblocks : 0);
    bool second = bx >= nb0;
    GemmJob J = second ? j1 : j0;
    int b = second ? bx - nb0 : bx;
    int rb, cb;
    if (J.colBlocks == 2) { rb = b >> 1; cb = b & 1; } else { rb = b; cb = 0; }
    int row0 = rb * 128;
    int colW = J.col0 + cb * NCOLS;

    int w = t >> 5, lane = t & 31;
    int mbase = (w >> 1) * 32;
    int nbase = (w & 1) * NH;
    int lrow = lane & 15;
    int lcolo = (lane >> 4) * 8;

    uint32_t a_base0 = (uint32_t)__cvta_generic_to_shared(&As[0][0]);
    uint32_t a_base1 = (uint32_t)__cvta_generic_to_shared(&As[1][0]);
    uint32_t b_base0 = (uint32_t)__cvta_generic_to_shared(&Bs[0][0]);
    uint32_t b_base1 = (uint32_t)__cvta_generic_to_shared(&Bs[1][0]);

    float acc[2][JN][4];
    #pragma unroll
    for (int i = 0; i < 2; i++)
        #pragma unroll
        for (int j = 0; j < JN; j++)
            #pragma unroll
            for (int q = 0; q < 4; q++) acc[i][j][q] = 0.f;

    for (int k0 = 0; k0 < DIN; k0 += 32) {
        #pragma unroll
        for (int ii = 0; ii < 4; ii++) {
            int idx = t + ii * 256;
            int r = idx >> 3, q = idx & 7;
            int grow = row0 + r;
            float4 v = make_float4(0.f, 0.f, 0.f, 0.f);
            if (grow < J.N) v = *(const float4*)(J.A + (size_t)grow * DIN + k0 + q * 4);
            if (AGELU) {
                v.x = gelu_exact(v.x); v.y = gelu_exact(v.y);
                v.z = gelu_exact(v.z); v.w = gelu_exact(v.w);
            }
            uint32_t h0, l0, h1, l1;
            split2(v.x, v.y, h0, l0);
            split2(v.z, v.w, h1, l1);
            *(uint2*)(&As[0][r * AS_STRIDE + q * 4]) = make_uint2(h0, h1);
            *(uint2*)(&As[1][r * AS_STRIDE + q * 4]) = make_uint2(l0, l1);
        }
        #pragma unroll
        for (int ii = 0; ii < NB; ii++) {
            int idx = t + ii * 256;
            int r = idx / BQ, q = idx % BQ;
            float4 v = *(const float4*)(J.B + (size_t)(k0 + r) * J.ldb + colW + q * 4);
            uint32_t h0, l0, h1, l1;
            split2(v.x, v.y, h0, l0);
            split2(v.z, v.w, h1, l1);
            *(uint2*)(&Bs[0][r * BSTR + q * 4]) = make_uint2(h0, h1);
            *(uint2*)(&Bs[1][r * BSTR + q * 4]) = make_uint2(l0, l1);
        }
        __syncthreads();

        #pragma unroll
        for (int kb = 0; kb < 32; kb += 16) {
            uint32_t ah[2][4], al[2][4];
            #pragma unroll
            for (int i = 0; i < 2; i++) {
                uint32_t off = (uint32_t)(((mbase + i * 16 + lrow) * AS_STRIDE + kb + lcolo) * 2);
                ldsm_x4(ah[i], a_base0 + off);
                ldsm_x4(al[i], a_base1 + off);
            }
            #pragma unroll
            for (int j2 = 0; j2 < J2N; j2++) {
                uint32_t bh[4], bl[4];
                uint32_t off = (uint32_t)(((kb + lrow) * BSTR + nbase + j2 * 16 + lcolo) * 2);
                ldsm_x4_t(bh, b_base0 + off);
                ldsm_x4_t(bl, b_base1 + off);
                #pragma unroll
                for (int i = 0; i < 2; i++)
                    #pragma unroll
                    for (int jj = 0; jj < 2; jj++) {
                        int j = j2 * 2 + jj, o = jj * 2;
                        mma_bf16(acc[i][j], ah[i], bh[o], bh[o + 1]);
                        mma_bf16(acc[i][j], ah[i], bl[o], bl[o + 1]);
                        mma_bf16(acc[i][j], al[i], bh[o], bh[o + 1]);
                    }
            }
        }
        __syncthreads();
    }

    int g = lane >> 2, tq = lane & 3;
    float amix = 0.f;
    if (POST == 2) amix = 1.f / (1.f + __expf(-skipv[0]));
    float fpart[2][2];
    if (FINAL) { fpart[0][0] = fpart[0][1] = fpart[1][0] = fpart[1][1] = 0.f; }
    #pragma unroll
    for (int i = 0; i < 2; i++) {
        #pragma unroll
        for (int j = 0; j < JN; j++) {
            int colg = colW + nbase + j * 8 + tq * 2;
            float b0 = J.bias[colg], b1 = J.bias[colg + 1];
            #pragma unroll
            for (int half = 0; half < 2; half++) {
                int row = row0 + mbase + i * 16 + g + half * 8;
                if (row < J.N) {
                    float o0 = acc[i][j][half * 2 + 0] + b0;
                    float o1 = acc[i][j][half * 2 + 1] + b1;
                    if (POST == 1) { o0 = fmaxf(o0, 0.f); o1 = fmaxf(o1, 0.f); }
                    if (POST == 2) {
                        o0 = amix * o0 + (1.f - amix) * J.x_in[(size_t)row * 64 + colg];
                        o1 = amix * o1 + (1.f - amix) * J.x_in[(size_t)row * 64 + colg + 1];
                    }
                    if (FINAL) {
                        fpart[i][half] += o0 * Wc[colg] + o1 * Wc[colg + 1];
                    } else if (J.outH != nullptr && colg >= 64) {
                        __half2 hv = __floats2half2_rn(o0, o1);
                        *(__half2*)(J.outH + (size_t)row * 128 + (colg - 64)) = hv;
                    } else {
                        *(float2*)(J.outF + (size_t)row * J.ldo + colg) = make_float2(o0, o1);
                    }
                }
            }
        }
    }
    if (FINAL) {
        #pragma unroll
        for (int i = 0; i < 2; i++)
            #pragma unroll
            for (int half = 0; half < 2; half++) {
                float pv = fpart[i][half];
                pv += __shfl_xor_sync(0xffffffffu, pv, 1);
                pv += __shfl_xor_sync(0xffffffffu, pv, 2);
                fpart[i][half] = pv;
            }
        if ((w & 1) == 0 && tq == 0) {
            #pragma unroll
            for (int i = 0; i < 2; i++)
                #pragma unroll
                for (int half = 0; half < 2; half++)
                    sred[mbase + i * 16 + g + half * 8] = fpart[i][half];
        }
        __syncthreads();
        if ((w & 1) == 1 && tq == 0) {
            #pragma unroll
            for (int i = 0; i < 2; i++)
                #pragma unroll
                for (int half = 0; half < 2; half++) {
                    int local = mbase + i * 16 + g + half * 8;
                    int row = row0 + local;
                    if (row < J.N)
                        J.outF[row] = sred[local] + fpart[i][half] + bc[0];
                }
        }
    }
}

// ---------------- fused L1-epilogue + L2-projection kernel ----------------
#define FA_STR 72   // 64 + 8 pad

struct FuseJob {
    const float* agg; const float* Wa; const float* ba;
    const float* W2;  const float* b2;   // W2 ldb = 192
    float* hOut;                          // fp32 h (tx) or nullptr
    float* qOut; __half* kvOut;           // GEMM2 output (one of them set)
    int N, colBlocks, col0;               // GEMM2 colW = col0 + cb*64
};

__global__ __launch_bounds__(256) void fuse_epi_proj_kernel(FuseJob j0, FuseJob j1, int nb0) {
    extern __shared__ __align__(16) char dsm[];
    bf16* Ah = (bf16*)dsm;                 // 128 x FA_STR
    bf16* Al = Ah + 128 * FA_STR;
    bf16* Bh = Al + 128 * FA_STR;          // 64 x FA_STR
    bf16* Bl = Bh + 64 * FA_STR;

    int t = threadIdx.x;
    int bx = blockIdx.x;
    bool second = bx >= nb0;
    FuseJob J = second ? j1 : j0;
    int b = second ? bx - nb0 : bx;
    int rb, cb;
    if (J.colBlocks == 2) { rb = b >> 1; cb = b & 1; } else { rb = b; cb = 0; }
    int row0 = rb * 128;
    int colW = J.col0 + cb * 64;

    int w = t >> 5, lane = t & 31;
    int mbase = (w >> 1) * 32;
    int nbase = (w & 1) * 32;
    int lrow = lane & 15;
    int lcolo = (lane >> 4) * 8;
    int g = lane >> 2, tq = lane & 3;

    uint32_t AhS = (uint32_t)__cvta_generic_to_shared(Ah);
    uint32_t AlS = (uint32_t)__cvta_generic_to_shared(Al);
    uint32_t BhS = (uint32_t)__cvta_generic_to_shared(Bh);
    uint32_t BlS = (uint32_t)__cvta_generic_to_shared(Bl);

    // ---- stage GEMM1 inputs ----
    #pragma unroll
    for (int ii = 0; ii < 8; ii++) {
        int idx = t + ii * 256;
        int r = idx >> 4, q = idx & 15;
        int grow = row0 + r;
        float4 v = make_float4(0.f, 0.f, 0.f, 0.f);
        if (grow < J.N) v = *(const float4*)(J.agg + (size_t)grow * 64 + q * 4);
        v.x = gelu_exact(v.x); v.y = gelu_exact(v.y);
        v.z = gelu_exact(v.z); v.w = gelu_exact(v.w);
        uint32_t h0, l0, h1, l1;
        split2(v.x, v.y, h0, l0);
        split2(v.z, v.w, h1, l1);
        *(uint2*)(&Ah[r * FA_STR + q * 4]) = make_uint2(h0, h1);
        *(uint2*)(&Al[r * FA_STR + q * 4]) = make_uint2(l0, l1);
    }
    #pragma unroll
    for (int ii = 0; ii < 4; ii++) {
        int idx = t + ii * 256;
        int r = idx >> 4, q = idx & 15;
        float4 v = *(const float4*)(J.Wa + (size_t)r * 64 + q * 4);
        uint32_t h0, l0, h1, l1;
        split2(v.x, v.y, h0, l0);
        split2(v.z, v.w, h1, l1);
        *(uint2*)(&Bh[r * FA_STR + q * 4]) = make_uint2(h0, h1);
        *(uint2*)(&Bl[r * FA_STR + q * 4]) = make_uint2(l0, l1);
    }
    __syncthreads();

    // ---- GEMM1 MMA: K = 64 ----
    float acc[2][4][4];
    #pragma unroll
    for (int i = 0; i < 2; i++)
        #pragma unroll
        for (int j = 0; j < 4; j++)
            #pragma unroll
            for (int q = 0; q < 4; q++) acc[i][j][q] = 0.f;

    #pragma unroll
    for (int kb = 0; kb < 64; kb += 16) {
        uint32_t ah[2][4], al[2][4];
        #pragma unroll
        for (int i = 0; i < 2; i++) {
            uint32_t off = (uint32_t)(((mbase + i * 16 + lrow) * FA_STR + kb + lcolo) * 2);
            ldsm_x4(ah[i], AhS + off);
            ldsm_x4(al[i], AlS + off);
        }
        #pragma unroll
        for (int j2 = 0; j2 < 2; j2++) {
            uint32_t bh[4], bl[4];
            uint32_t off = (uint32_t)(((kb + lrow) * FA_STR + nbase + j2 * 16 + lcolo) * 2);
            ldsm_x4_t(bh, BhS + off);
            ldsm_x4_t(bl, BlS + off);
            #pragma unroll
            for (int i = 0; i < 2; i++)
                #pragma unroll
                for (int jj = 0; jj < 2; jj++) {
                    int j = j2 * 2 + jj, o = jj * 2;
                    mma_bf16(acc[i][j], ah[i], bh[o], bh[o + 1]);
                    mma_bf16(acc[i][j], ah[i], bl[o], bl[o + 1]);
                    mma_bf16(acc[i][j], al[i], bh[o], bh[o + 1]);
                }
        }
    }
    __syncthreads();

    // ---- epilogue1 + restage ----
    #pragma unroll
    for (int i = 0; i < 2; i++) {
        #pragma unroll
        for (int j = 0; j < 4; j++) {
            int col = nbase + j * 8 + tq * 2;
            float b0 = J.ba[col], b1 = J.ba[col + 1];
            #pragma unroll
            for (int half = 0; half < 2; half++) {
                int lrowi = mbase + i * 16 + g + half * 8;
                int row = row0 + lrowi;
                float o0 = fmaxf(acc[i][j][half * 2 + 0] + b0, 0.f);
                float o1 = fmaxf(acc[i][j][half * 2 + 1] + b1, 0.f);
                if (J.hOut != nullptr && row < J.N)
                    *(float2*)(J.hOut + (size_t)row * 64 + col) = make_float2(o0, o1);
                uint32_t hv, lv;
                split2(o0, o1, hv, lv);
                *(uint32_t*)(&Ah[lrowi * FA_STR + col]) = hv;
                *(uint32_t*)(&Al[lrowi * FA_STR + col]) = lv;
            }
        }
    }
    #pragma unroll
    for (int ii = 0; ii < 4; ii++) {
        int idx = t + ii * 256;
        int r = idx >> 4, q = idx & 15;
        float4 v = *(const float4*)(J.W2 + (size_t)r * 192 + colW + q * 4);
        uint32_t h0, l0, h1, l1;
        split2(v.x, v.y, h0, l0);
        split2(v.z, v.w, h1, l1);
        *(uint2*)(&Bh[r * FA_STR + q * 4]) = make_uint2(h0, h1);
        *(uint2*)(&Bl[r * FA_STR + q * 4]) = make_uint2(l0, l1);
    }
    __syncthreads();

    // ---- GEMM2 MMA: K = 64 ----
    #pragma unroll
    for (int i = 0; i < 2; i++)
        #pragma unroll
        for (int j = 0; j < 4; j++)
            #pragma unroll
            for (int q = 0; q < 4; q++) acc[i][j][q] = 0.f;

    #pragma unroll
    for (int kb = 0; kb < 64; kb += 16) {
        uint32_t ah[2][4], al[2][4];
        #pragma unroll
        for (int i = 0; i < 2; i++) {
            uint32_t off = (uint32_t)(((mbase + i * 16 + lrow) * FA_STR + kb + lcolo) * 2);
            ldsm_x4(ah[i], AhS + off);
            ldsm_x4(al[i], AlS + off);
        }
        #pragma unroll
        for (int j2 = 0; j2 < 2; j2++) {
            uint32_t bh[4], bl[4];
            uint32_t off = (uint32_t)(((kb + lrow) * FA_STR + nbase + j2 * 16 + lcolo) * 2);
            ldsm_x4_t(bh, BhS + off);
            ldsm_x4_t(bl, BlS + off);
            #pragma unroll
            for (int i = 0; i < 2; i++)
                #pragma unroll
                for (int jj = 0; jj < 2; jj++) {
                    int j = j2 * 2 + jj, o = jj * 2;
                    mma_bf16(acc[i][j], ah[i], bh[o], bh[o + 1]);
                    mma_bf16(acc[i][j], ah[i], bl[o], bl[o + 1]);
                    mma_bf16(acc[i][j], al[i], bh[o], bh[o + 1]);
                }
        }
    }

    // ---- epilogue2 ----
    #pragma unroll
    for (int i = 0; i < 2; i++) {
        #pragma unroll
        for (int j = 0; j < 4; j++) {
            int col = nbase + j * 8 + tq * 2;
            int colg = colW + col;
            float b0 = J.b2[colg], b1 = J.b2[colg + 1];
            #pragma unroll
            for (int half = 0; half < 2; half++) {
                int row = row0 + mbase + i * 16 + g + half * 8;
                if (row < J.N) {
                    float o0 = acc[i][j][half * 2 + 0] + b0;
                    float o1 = acc[i][j][half * 2 + 1] + b1;
                    if (J.kvOut != nullptr) {
                        __half2 hv = __floats2half2_rn(o0, o1);
                        *(__half2*)(J.kvOut + (size_t)row * 128 + (colg - 64)) = hv;
                    } else {
                        *(float2*)(J.qOut + (size_t)row * 64 + colg) = make_float2(o0, o1);
                    }
                }
            }
        }
    }
}

// ---------------- attention: srcs-prefetch + occupancy-4 ----------------
struct AttnSet {
    const __half* kv; const float* q;
    const int* rp; const int* srcs;
    const float* prel; float* agg; int n;
};

__global__ __launch_bounds__(256, 4) void attn_kernel(AttnSet s0, AttnSet s1) {
    int w = threadIdx.x >> 5, lane = threadIdx.x & 31;
    int d = blockIdx.x * 8 + w;
    AttnSet S;
    int dst;
    if (d < s0.n) { S = s0; dst = d; }
    else {
        dst = d - s0.n;
        if (dst >= s1.n) return;
        S = s1;
    }
    int sub = lane & 7;
    int eg = lane >> 3;
    const float* qd = S.q + (size_t)dst * 64 + sub * 8;
    float4 q0 = *(const float4*)(qd);
    float4 q1 = *(const float4*)(qd + 4);
    float pr = S.prel[sub >> 1] * 0.25f;   // /SQRT_D folded
    float4 a0 = make_float4(0.f, 0.f, 0.f, 0.f);
    float4 a1 = make_float4(0.f, 0.f, 0.f, 0.f);
    float den = 0.f;
    int beg = S.rp[dst], end = S.rp[dst + 1];
    if (beg < end) {
        int ei0 = beg + eg;
        int scur = S.srcs[ei0 < end ? ei0 : beg];
        for (int i = beg; i < end; i += 4) {
            // prefetch next group's src index: breaks the srcs->kv latency chain
            int einext = i + 4 + eg;
            int snext = S.srcs[einext < end ? einext : beg];
            bool valid = (i + eg) < end;
            const __half* ps = S.kv + (size_t)scur * 128 + sub * 8;
            uint4 kraw = *(const uint4*)(ps);        // 8 halfs: K slice
            uint4 vraw = *(const uint4*)(ps + 64);   // 8 halfs: V slice
            float2 k0 = __half22float2(*(__half2*)&kraw.x);
            float2 k1 = __half22float2(*(__half2*)&kraw.y);
            float2 k2 = __half22float2(*(__half2*)&kraw.z);
            float2 k3 = __half22float2(*(__half2*)&kraw.w);
            float part = q0.x * k0.x + q0.y * k0.y + q0.z * k1.x + q0.w * k1.y
                       + q1.x * k2.x + q1.y * k2.y + q1.z * k3.x + q1.w * k3.y;
            part += __shfl_xor_sync(0xffffffffu, part, 1);
            float e = valid ? __expf(part * pr) : 0.f;
            float2 v0 = __half22float2(*(__half2*)&vraw.x);
            float2 v1 = __half22float2(*(__half2*)&vraw.y);
            float2 v2 = __half22float2(*(__half2*)&vraw.z);
            float2 v3 = __half22float2(*(__half2*)&vraw.w);
            a0.x = fmaf(e, v0.x, a0.x); a0.y = fmaf(e, v0.y, a0.y);
            a0.z = fmaf(e, v1.x, a0.z); a0.w = fmaf(e, v1.y, a0.w);
            a1.x = fmaf(e, v2.x, a1.x); a1.y = fmaf(e, v2.y, a1.y);
            a1.z = fmaf(e, v3.x, a1.z); a1.w = fmaf(e, v3.y, a1.w);
            den += e;
            scur = snext;
        }
    }
    #pragma unroll
    for (int off = 8; off <= 16; off <<= 1) {
        a0.x += __shfl_xor_sync(0xffffffffu, a0.x, off);
        a0.y += __shfl_xor_sync(0xffffffffu, a0.y, off);
        a0.z += __shfl_xor_sync(0xffffffffu, a0.z, off);
        a0.w += __shfl_xor_sync(0xffffffffu, a0.w, off);
        a1.x += __shfl_xor_sync(0xffffffffu, a1.x, off);
        a1.y += __shfl_xor_sync(0xffffffffu, a1.y, off);
        a1.z += __shfl_xor_sync(0xffffffffu, a1.z, off);
        a1.w += __shfl_xor_sync(0xffffffffu, a1.w, off);
        den  += __shfl_xor_sync(0xffffffffu, den, off);
    }
    if (lane < 8) {
        float inv = 1.f / (den + 1e-16f);
        a0.x *= inv; a0.y *= inv; a0.z *= inv; a0.w *= inv;
        a1.x *= inv; a1.y *= inv; a1.z *= inv; a1.w *= inv;
        float* op = S.agg + (size_t)dst * 64 + sub * 8;
        *(float4*)(op) = a0;
        *(float4*)(op + 4) = a1;
    }
}

// ---------------- launch ----------------
extern "C" void kernel_launch(void* const* d_in, const int* in_sizes, int n_in,
                              void* d_out, int out_size) {
    (void)n_in; (void)out_size;
    int ebase, wbase;
    if (in_sizes[2] > 100000) { ebase = 2;  wbase = 6; }
    else                      { ebase = 27; wbase = 2; }

    const float* x_tx = (const float*)d_in[0];
    const float* x_m  = (const float*)d_in[1];
    const int* tm_src = (const int*)d_in[ebase + 0];
    const int* tm_dst = (const int*)d_in[ebase + 1];
    const int* mt_src = (const int*)d_in[ebase + 2];
    const int* mt_dst = (const int*)d_in[ebase + 3];

    const float* c1_Wk    = (const float*)d_in[wbase + 0];
    const float* c1_bk    = (const float*)d_in[wbase + 1];
    const float* c1_Wq    = (const float*)d_in[wbase + 2];
    const float* c1_bq    = (const float*)d_in[wbase + 3];
    const float* c1_Wv    = (const float*)d_in[wbase + 4];
    const float* c1_bv    = (const float*)d_in[wbase + 5];
    const float* c1_a_rel = (const float*)d_in[wbase + 6];
    const float* c1_m_rel = (const float*)d_in[wbase + 7];
    const float* c1_p_rel = (const float*)d_in[wbase + 8];
    const float* c1_Wa    = (const float*)d_in[wbase + 9];
    const float* c1_ba    = (const float*)d_in[wbase + 10];
    const float* c2_Wk    = (const float*)d_in[wbase + 11];
    const float* c2_bk    = (const float*)d_in[wbase + 12];
    const float* c2_Wq    = (const float*)d_in[wbase + 13];
    const float* c2_bq    = (const float*)d_in[wbase + 14];
    const float* c2_Wv    = (const float*)d_in[wbase + 15];
    const float* c2_bv    = (const float*)d_in[wbase + 16];
    const float* c2_a_rel = (const float*)d_in[wbase + 17];
    const float* c2_m_rel = (const float*)d_in[wbase + 18];
    const float* c2_p_rel = (const float*)d_in[wbase + 19];
    const float* c2_Wa    = (const float*)d_in[wbase + 20];
    const float* c2_ba    = (const float*)d_in[wbase + 21];
    const float* c2_skip  = (const float*)d_in[wbase + 22];
    const float* Wc       = (const float*)d_in[wbase + 23];
    const float* bc       = (const float*)d_in[wbase + 24];

    int N_TX = in_sizes[0] / 128;
    int N_M  = in_sizes[1] / 128;
    int E0 = in_sizes[ebase + 1];
    int E1 = in_sizes[ebase + 3];

    void* p;
    float *q_tx, *q_m, *agg_tx, *agg_m, *h_tx;
    float *WA1, *bA1, *WB1, *bB1, *WA2, *bA2, *WB2, *bB2;
    __half *kv_tx, *kv_m;
    int *rowptr0, *rowptr1, *cursor0, *cursor1, *srcs0, *srcs1;
    cudaGetSymbolAddress(&p, g_q_tx);    q_tx    = (float*)p;
    cudaGetSymbolAddress(&p, g_q_m);     q_m     = (float*)p;
    cudaGetSymbolAddress(&p, g_kv_tx);   kv_tx   = (__half*)p;
    cudaGetSymbolAddress(&p, g_kv_m);    kv_m    = (__half*)p;
    cudaGetSymbolAddress(&p, g_agg_tx);  agg_tx  = (float*)p;
    cudaGetSymbolAddress(&p, g_agg_m);   agg_m   = (float*)p;
    cudaGetSymbolAddress(&p, g_h_tx);    h_tx    = (float*)p;
    cudaGetSymbolAddress(&p, g_WA1);     WA1     = (float*)p;
    cudaGetSymbolAddress(&p, g_bA1);     bA1     = (float*)p;
    cudaGetSymbolAddress(&p, g_WB1);     WB1     = (float*)p;
    cudaGetSymbolAddress(&p, g_bB1);     bB1     = (float*)p;
    cudaGetSymbolAddress(&p, g_WA2);     WA2     = (float*)p;
    cudaGetSymbolAddress(&p, g_bA2);     bA2     = (float*)p;
    cudaGetSymbolAddress(&p, g_WB2);     WB2     = (float*)p;
    cudaGetSymbolAddress(&p, g_bB2);     bB2     = (float*)p;
    cudaGetSymbolAddress(&p, g_rowptr0); rowptr0 = (int*)p;
    cudaGetSymbolAddress(&p, g_rowptr1); rowptr1 = (int*)p;
    cudaGetSymbolAddress(&p, g_cursor0); cursor0 = (int*)p;
    cudaGetSymbolAddress(&p, g_cursor1); cursor1 = (int*)p;
    cudaGetSymbolAddress(&p, g_srcs0);   srcs0   = (int*)p;
    cudaGetSymbolAddress(&p, g_srcs1);   srcs1   = (int*)p;

    int gbTX = (N_TX + 127) / 128;
    int gbM  = (N_M + 127) / 128;

    ScatJob sjNone = {};
    sjNone.nblocks = 0;

    // ---- 1: effective weights + cursor zeroing ----
    {
        int zx = (N_M + N_TX + 255) / 256;
        int gx = zx > 97 ? zx : 97;
        eff_all_kernel<<<dim3(gx, 5), 256>>>(
            c1_Wq, c1_bq, c1_Wk, c1_bk, c1_Wv, c1_bv, c1_a_rel, c1_m_rel,
            c2_Wq, c2_bq, c2_Wk, c2_bk, c2_Wv, c2_bv, c2_a_rel, c2_m_rel,
            WA1, bA1, WB1, bB1, WA2, bA2, WB2, bB2,
            cursor0, N_M, cursor1, N_TX);
    }

    // ---- 2-3: hist + scan ----
    hist_both_kernel<<<(E0 + E1 + 255) / 256, 256>>>(tm_dst, E0, cursor0, mt_dst, E1, cursor1);
    scan_both_kernel<<<2, 1024>>>(cursor0, rowptr0, N_M, cursor1, rowptr1, N_TX);

    // ---- 4: scatter + layer-1 QKV GEMM fused (128 x 96 tiles) ----
    {
        ScatJob sj = { tm_src, tm_dst, E0, cursor0, srcs0,
                       mt_src, mt_dst, E1, cursor1, srcs1,
                       (E0 + E1 + 255) / 256 };
        GemmJob j0 = { x_tx, WA1, bA1, nullptr, q_tx, kv_tx, N_TX, 192, 0, 64, 2 };
        GemmJob j1 = { x_m,  WB1, bB1, nullptr, q_m,  kv_m,  N_M,  192, 0, 64, 2 };
        int nb0 = gbTX * 2;
        mma_gemm_kernel<0, 0, 96, 1, 0><<<sj.nblocks + nb0 + gbM * 2, 256>>>(
            j0, j1, nb0, 128, nullptr, sj, nullptr, nullptr);
    }

    // ---- 5: layer-1 attention, both directions merged ----
    {
        AttnSet s0 = { kv_tx, q_m,  rowptr0, srcs0, c1_p_rel,     agg_m,  N_M };
        AttnSet s1 = { kv_m,  q_tx, rowptr1, srcs1, c1_p_rel + 4, agg_tx, N_TX };
        attn_kernel<<<(N_M + N_TX + 7) / 8, 256>>>(s0, s1);
    }

    // ---- 6: FUSED layer-1 epilogue + layer-2 projection ----
    {
        const int DSM = (2 * 128 * FA_STR + 2 * 64 * FA_STR) * 2;  // 55296 B
        cudaFuncSetAttribute(fuse_epi_proj_kernel,
                             cudaFuncAttributeMaxDynamicSharedMemorySize, DSM);
        FuseJob j0 = { agg_tx, c1_Wa,        c1_ba,      WA2, bA2, h_tx,
                       q_tx, nullptr, N_TX, 1, 0 };
        FuseJob j1 = { agg_m,  c1_Wa + 4096, c1_ba + 64, WB2, bB2, nullptr,
                       nullptr, kv_m, N_M, 2, 64 };
        fuse_epi_proj_kernel<<<gbTX + gbM * 2, 256, DSM>>>(j0, j1, gbTX);
    }

    // ---- 7: layer-2 attention (tx dst only) ----
    {
        AttnSet s1 = { kv_m, q_tx, rowptr1, srcs1, c2_p_rel + 4, agg_tx, N_TX };
        AttnSet s0 = s1; s0.n = 0;
        attn_kernel<<<(N_TX + 7) / 8, 256>>>(s0, s1);
    }

    // ---- 8: layer-2 epilogue + skip mix + fused final logits -> d_out ----
    {
        GemmJob j0 = { agg_tx, c2_Wa, c2_ba, h_tx, (float*)d_out, nullptr, N_TX, 64, 0, 1, 1 };
        mma_gemm_kernel<2, 1, 64, 0, 1><<<gbTX, 256>>>(
            j0, j0, gbTX, 64, c2_skip, sjNone, Wc, bc);
    }
}